// round 14
// baseline (speedup 1.0000x reference)
#include <cuda_runtime.h>
#include <cuda_fp16.h>
#include <math.h>
#include <stdint.h>

#define N_NODES 4096
#define F_IN    256
#define F_OUT   512
#define HEADS   8
#define DH      64
#define LOG2E   1.4426950408889634f
#define MAGICF  12582912.0f          // 1.5 * 2^23

#define KTILE   64
#define NT      (N_NODES / KTILE)   // 64 key tiles
#define QTILE   64                  // q rows per block (16 per warp)
#define PITCH   144                 // bytes per 64-fp16 row (conflict-free)
#define STG     (KTILE * PITCH)     // 9216 bytes per K stage
#define SMEM_SZ (2 * STG)           // 18432 (K double-buffer; Q staged through stage0)

#define N_X (N_NODES * F_IN)
#define N_W (F_OUT * F_IN)
#define N_A (HEADS * DH * DH)

typedef unsigned long long u64;

// ---------------- device scratch (no allocs allowed) ----------------
__device__ __align__(256) __half g_xh[N_X], g_xl[N_X];
__device__ __align__(256) __half g_wh[N_W], g_wl[N_W];
__device__ __align__(256) __half g_ah[N_A], g_al[N_A];
__device__ __align__(256) __half g_hh[N_NODES * F_OUT];   // fp16(h)  (K == V)
__device__ __align__(256) __half g_hl[N_NODES * F_OUT];   // fp16 residual of h
__device__ __align__(256) __half g_qh[N_NODES * F_OUT];   // fp16(q * log2e)

// ---------------- helpers ----------------
__device__ __forceinline__ uint32_t smem_u32(const void* p) {
    uint32_t a;
    asm("{ .reg .u64 t; cvta.to.shared.u64 t, %1; cvt.u32.u64 %0, t; }" : "=r"(a) : "l"(p));
    return a;
}
__device__ __forceinline__ uint32_t hfpk(float a, float b) {
    uint32_t r; asm("cvt.rn.f16x2.f32 %0, %1, %2;" : "=r"(r) : "f"(b), "f"(a)); return r;
}
__device__ __forceinline__ u64 pk2(float lo, float hi) {
    u64 r; asm("mov.b64 %0, {%1, %2};" : "=l"(r) : "f"(lo), "f"(hi)); return r;
}
__device__ __forceinline__ u64 dup2(float v) {
    u64 r; asm("mov.b64 %0, {%1, %1};" : "=l"(r) : "f"(v)); return r;
}
__device__ __forceinline__ void unp2(u64 v, float& lo, float& hi) {
    asm("mov.b64 {%0, %1}, %2;" : "=f"(lo), "=f"(hi) : "l"(v));
}
__device__ __forceinline__ u64 add2(u64 a, u64 b) {
    u64 r; asm("add.rn.f32x2 %0, %1, %2;" : "=l"(r) : "l"(a), "l"(b)); return r;
}
__device__ __forceinline__ u64 fma2_(u64 a, u64 b, u64 c) {
    u64 r; asm("fma.rn.f32x2 %0, %1, %2, %3;" : "=l"(r) : "l"(a), "l"(b), "l"(c)); return r;
}

// packed softmax: p = 2^(leaky(v) - 6) for a pair; accumulates lsum; returns fp16x2
__device__ __forceinline__ uint32_t softmax_pair(float c0, float c1, float& lacc) {
    u64 v2 = pk2(c0, c1);
    u64 y2 = fma2_(v2, dup2(0.6f), dup2(-6.0f));        // 0.6v - 6
    u64 a2 = v2 & 0x7FFFFFFF7FFFFFFFull;                // |v|
    y2 = fma2_(a2, dup2(0.4f), y2);                     // leaky - 6
    u64 fn2 = add2(y2, dup2(MAGICF));
    u64 t2  = fma2_(fn2, dup2(1.0f), dup2(-MAGICF));    // round(y)
    u64 f2  = fma2_(t2, dup2(-1.0f), y2);               // frac in [-0.5, 0.5]
    u64 p2  = fma2_(f2, dup2(0.00961813f), dup2(0.05550411f));
    p2 = fma2_(p2, f2, dup2(0.24022651f));
    p2 = fma2_(p2, f2, dup2(0.69314718f));
    p2 = fma2_(p2, f2, dup2(1.0f));
    float pf0, pf1, ff0, ff1;
    unp2(p2, pf0, pf1);
    unp2(fn2, ff0, ff1);
    float e0 = __int_as_float(__float_as_int(pf0) + (__float_as_int(ff0) << 23));
    float e1 = __int_as_float(__float_as_int(pf1) + (__float_as_int(ff1) << 23));
    lacc += e0 + e1;
    return hfpk(e0, e1);
}

__device__ __forceinline__ void cpa16(uint32_t dst, const void* src) {
    asm volatile("cp.async.cg.shared.global [%0], [%1], 16;" :: "r"(dst), "l"(src) : "memory");
}
#define CP_COMMIT() asm volatile("cp.async.commit_group;" ::: "memory")
#define CP_WAIT0()  asm volatile("cp.async.wait_group 0;" ::: "memory")

__device__ __forceinline__ void ldsm4(uint32_t a, uint32_t& r0, uint32_t& r1,
                                      uint32_t& r2, uint32_t& r3) {
    asm volatile("ldmatrix.sync.aligned.m8n8.x4.shared.b16 {%0,%1,%2,%3}, [%4];"
                 : "=r"(r0), "=r"(r1), "=r"(r2), "=r"(r3) : "r"(a));
}
__device__ __forceinline__ void ldsm4t(uint32_t a, uint32_t& r0, uint32_t& r1,
                                       uint32_t& r2, uint32_t& r3) {
    asm volatile("ldmatrix.sync.aligned.m8n8.x4.trans.shared.b16 {%0,%1,%2,%3}, [%4];"
                 : "=r"(r0), "=r"(r1), "=r"(r2), "=r"(r3) : "r"(a));
}
__device__ __forceinline__ void mma16816(float* c, const uint32_t* a, uint32_t b0, uint32_t b1) {
    asm volatile(
        "mma.sync.aligned.m16n8k16.row.col.f32.f16.f16.f32 "
        "{%0,%1,%2,%3}, {%4,%5,%6,%7}, {%8,%9}, {%0,%1,%2,%3};"
        : "+f"(c[0]), "+f"(c[1]), "+f"(c[2]), "+f"(c[3])
        : "r"(a[0]), "r"(a[1]), "r"(a[2]), "r"(a[3]), "r"(b0), "r"(b1));
}

// ---------------------------------------------------------------------------
// Kernel 0: convert x, W, A to fp16 hi/lo pairs.
// ---------------------------------------------------------------------------
__global__ __launch_bounds__(256) void k_cvt(const float* __restrict__ X,
                                             const float* __restrict__ W,
                                             const float* __restrict__ A) {
    const int i = (blockIdx.x * 256 + threadIdx.x) * 2;
    const float* src; __half *dh, *dl; int off;
    if (i < N_X)            { src = X; dh = g_xh; dl = g_xl; off = i; }
    else if (i < N_X + N_W) { src = W; dh = g_wh; dl = g_wl; off = i - N_X; }
    else                    { src = A; dh = g_ah; dl = g_al; off = i - N_X - N_W; }
    float2 v = *(const float2*)&src[off];
    uint32_t hp = hfpk(v.x, v.y);
    __half2 h2 = *(__half2*)&hp;
    uint32_t lp = hfpk(v.x - __low2float(h2), v.y - __high2float(h2));
    *(uint32_t*)&dh[off] = hp;
    *(uint32_t*)&dl[off] = lp;
}

// ---------------------------------------------------------------------------
// Kernel 1: h = x @ W^T via 3-term compensated fp16 mma. (unchanged)
// ---------------------------------------------------------------------------
#define P80     80
#define MM1_XH  0
#define MM1_XL  10240
#define MM1_WH  20480
#define MM1_WL  25600
#define MM1_SZ  30720

__global__ __launch_bounds__(128) void k_mm1() {
    __shared__ __align__(16) char smem[MM1_SZ];
    const uint32_t sb = smem_u32(smem);
    const int tid = threadIdx.x, w = tid >> 5, lane = tid & 31;
    const int m0 = blockIdx.x * 128, o0 = blockIdx.y * 64;
    const int lm = lane >> 3, lr = lane & 7;
    const int sKey = ((lm >> 1) << 3) + lr;
    const int sD   = (lm & 1) << 3;
    const int qRow = ((lm & 1) << 3) + lr;
    const int qCol = (lm >> 1) << 3;

    float oc[2][8][4] = {};

    for (int kc = 0; kc < F_IN / 32; kc++) {
        const int k0 = kc * 32;
        {
            const __half* xh = &g_xh[(size_t)(m0 + tid) * F_IN + k0];
            const __half* xl = &g_xl[(size_t)(m0 + tid) * F_IN + k0];
            const uint32_t dxh = sb + MM1_XH + tid * P80;
            const uint32_t dxl = sb + MM1_XL + tid * P80;
            #pragma unroll
            for (int c = 0; c < 4; c++) {
                cpa16(dxh + c * 16, xh + c * 8);
                cpa16(dxl + c * 16, xl + c * 8);
            }
            const int r = tid & 63;
            const __half* ws = (tid < 64) ? &g_wh[(size_t)(o0 + r) * F_IN + k0]
                                          : &g_wl[(size_t)(o0 + r) * F_IN + k0];
            const uint32_t dw = sb + ((tid < 64) ? MM1_WH : MM1_WL) + r * P80;
            #pragma unroll
            for (int c = 0; c < 4; c++) cpa16(dw + c * 16, ws + c * 8);
        }
        CP_COMMIT(); CP_WAIT0(); __syncthreads();

        uint32_t ah[4][4], al[4][4];
        #pragma unroll
        for (int m = 0; m < 2; m++) {
            const uint32_t bh = sb + MM1_XH + (w * 32 + m * 16 + qRow) * P80 + qCol * 2;
            const uint32_t bl = sb + MM1_XL + (w * 32 + m * 16 + qRow) * P80 + qCol * 2;
            #pragma unroll
            for (int s = 0; s < 2; s++) {
                ldsm4(bh + s * 32, ah[s * 2 + m][0], ah[s * 2 + m][1],
                                   ah[s * 2 + m][2], ah[s * 2 + m][3]);
                ldsm4(bl + s * 32, al[s * 2 + m][0], al[s * 2 + m][1],
                                   al[s * 2 + m][2], al[s * 2 + m][3]);
            }
        }
        #pragma unroll
        for (int s = 0; s < 2; s++) {
            #pragma unroll
            for (int u = 0; u < 4; u++) {
                uint32_t bh0, bh1, bh2, bh3, bl0, bl1, bl2, bl3;
                ldsm4(sb + MM1_WH + (u * 16 + sKey) * P80 + s * 32 + sD * 2, bh0, bh1, bh2, bh3);
                ldsm4(sb + MM1_WL + (u * 16 + sKey) * P80 + s * 32 + sD * 2, bl0, bl1, bl2, bl3);
                #pragma unroll
                for (int m = 0; m < 2; m++) {
                    mma16816(oc[m][2 * u],     ah[s * 2 + m], bh0, bh1);
                    mma16816(oc[m][2 * u],     al[s * 2 + m], bh0, bh1);
                    mma16816(oc[m][2 * u],     ah[s * 2 + m], bl0, bl1);
                    mma16816(oc[m][2 * u + 1], ah[s * 2 + m], bh2, bh3);
                    mma16816(oc[m][2 * u + 1], al[s * 2 + m], bh2, bh3);
                    mma16816(oc[m][2 * u + 1], ah[s * 2 + m], bl2, bl3);
                }
            }
        }
        __syncthreads();
    }

    const int g = lane >> 2, tg = lane & 3;
    #pragma unroll
    for (int m = 0; m < 2; m++) {
        const int rowA = m0 + w * 32 + m * 16 + g;
        #pragma unroll
        for (int j = 0; j < 8; j++) {
            const int col = o0 + j * 8 + 2 * tg;
            float a0 = oc[m][j][0], a1 = oc[m][j][1];
            uint32_t hp = hfpk(a0, a1);
            __half2 h2 = *(__half2*)&hp;
            *(uint32_t*)&g_hh[(size_t)rowA * F_OUT + col] = hp;
            *(uint32_t*)&g_hl[(size_t)rowA * F_OUT + col] =
                hfpk(a0 - __low2float(h2), a1 - __high2float(h2));
            float b0 = oc[m][j][2], b1 = oc[m][j][3];
            uint32_t hp2 = hfpk(b0, b1);
            __half2 h22 = *(__half2*)&hp2;
            *(uint32_t*)&g_hh[(size_t)(rowA + 8) * F_OUT + col] = hp2;
            *(uint32_t*)&g_hl[(size_t)(rowA + 8) * F_OUT + col] =
                hfpk(b0 - __low2float(h22), b1 - __high2float(h22));
        }
    }
}

// ---------------------------------------------------------------------------
// Kernel 2: q = (h @ A) * log2e via 3-term compensated fp16 mma. (unchanged)
// ---------------------------------------------------------------------------
#define MM2_HH  0
#define MM2_HL  10240
#define MM2_AH  20480
#define MM2_AL  29696
#define MM2_SZ  38912

__global__ __launch_bounds__(128) void k_mm2() {
    __shared__ __align__(16) char smem[MM2_SZ];
    const uint32_t sb = smem_u32(smem);
    const int tid = threadIdx.x, w = tid >> 5, lane = tid & 31;
    const int m0 = blockIdx.x * 128, head = blockIdx.y, hb = head * DH;
    const int lm = lane >> 3, lr = lane & 7;
    const int vKey = ((lm & 1) << 3) + lr;
    const int vD   = (lm >> 1) << 3;
    const int qRow = ((lm & 1) << 3) + lr;
    const int qCol = (lm >> 1) << 3;

    {
        const int r = tid & 63;
        const __half* as = (tid < 64) ? &g_ah[(size_t)head * DH * DH + r * DH]
                                      : &g_al[(size_t)head * DH * DH + r * DH];
        const uint32_t da = sb + ((tid < 64) ? MM2_AH : MM2_AL) + r * PITCH;
        #pragma unroll
        for (int c = 0; c < 8; c++) cpa16(da + c * 16, as + c * 8);
    }

    float oc[2][8][4] = {};

    for (int kc = 0; kc < 2; kc++) {
        {
            const __half* hh = &g_hh[(size_t)(m0 + tid) * F_OUT + hb + kc * 32];
            const __half* hl = &g_hl[(size_t)(m0 + tid) * F_OUT + hb + kc * 32];
            const uint32_t dh = sb + MM2_HH + tid * P80;
            const uint32_t dl = sb + MM2_HL + tid * P80;
            #pragma unroll
            for (int c = 0; c < 4; c++) {
                cpa16(dh + c * 16, hh + c * 8);
                cpa16(dl + c * 16, hl + c * 8);
            }
        }
        CP_COMMIT(); CP_WAIT0(); __syncthreads();

        uint32_t ah[4][4], al[4][4];
        #pragma unroll
        for (int m = 0; m < 2; m++) {
            const uint32_t bh = sb + MM2_HH + (w * 32 + m * 16 + qRow) * P80 + qCol * 2;
            const uint32_t bl = sb + MM2_HL + (w * 32 + m * 16 + qRow) * P80 + qCol * 2;
            #pragma unroll
            for (int s = 0; s < 2; s++) {
                ldsm4(bh + s * 32, ah[s * 2 + m][0], ah[s * 2 + m][1],
                                   ah[s * 2 + m][2], ah[s * 2 + m][3]);
                ldsm4(bl + s * 32, al[s * 2 + m][0], al[s * 2 + m][1],
                                   al[s * 2 + m][2], al[s * 2 + m][3]);
            }
        }
        #pragma unroll
        for (int s = 0; s < 2; s++) {
            const int kglob = kc * 32 + s * 16;
            #pragma unroll
            for (int u = 0; u < 4; u++) {
                uint32_t bh0, bh1, bh2, bh3, bl0, bl1, bl2, bl3;
                ldsm4t(sb + MM2_AH + (kglob + vKey) * PITCH + (u * 16 + vD) * 2, bh0, bh1, bh2, bh3);
                ldsm4t(sb + MM2_AL + (kglob + vKey) * PITCH + (u * 16 + vD) * 2, bl0, bl1, bl2, bl3);
                #pragma unroll
                for (int m = 0; m < 2; m++) {
                    mma16816(oc[m][2 * u],     ah[s * 2 + m], bh0, bh1);
                    mma16816(oc[m][2 * u],     al[s * 2 + m], bh0, bh1);
                    mma16816(oc[m][2 * u],     ah[s * 2 + m], bl0, bl1);
                    mma16816(oc[m][2 * u + 1], ah[s * 2 + m], bh2, bh3);
                    mma16816(oc[m][2 * u + 1], al[s * 2 + m], bh2, bh3);
                    mma16816(oc[m][2 * u + 1], ah[s * 2 + m], bl2, bl3);
                }
            }
        }
        __syncthreads();
    }

    const int g = lane >> 2, tg = lane & 3;
    #pragma unroll
    for (int m = 0; m < 2; m++) {
        const int rowA = m0 + w * 32 + m * 16 + g;
        #pragma unroll
        for (int j = 0; j < 8; j++) {
            const int col = hb + j * 8 + 2 * tg;
            *(uint32_t*)&g_qh[(size_t)rowA * F_OUT + col] =
                hfpk(oc[m][j][0] * LOG2E, oc[m][j][1] * LOG2E);
            *(uint32_t*)&g_qh[(size_t)(rowA + 8) * F_OUT + col] =
                hfpk(oc[m][j][2] * LOG2E, oc[m][j][3] * LOG2E);
        }
    }
}

// ---------------------------------------------------------------------------
// Kernel 3: fp16 flash attention, latency-optimized:
// 16 q rows/warp, QTILE 64, 4 blocks/SM (16 warps/SM = 4 per SMSP), single
// balanced wave. Q fragments in registers; packed-f32x2 softmax; S(u+1)
// pipelined ahead of softmax(u).
// ---------------------------------------------------------------------------
#define S_BLOCK(uu)                                                              \
    do {                                                                         \
        const int par_ = (uu) & 1;                                               \
        _Pragma("unroll")                                                        \
        for (int k2 = 0; k2 < 4; k2++) { sc[par_][0][k2] = 0.f; sc[par_][1][k2] = 0.f; } \
        _Pragma("unroll")                                                        \
        for (int s2 = 0; s2 < 4; s2++) {                                         \
            uint32_t kf0, kf1, kf2, kf3;                                         \
            ldsm4(sAddr + (16 * (uu)) * PITCH + (16 * s2) * 2, kf0, kf1, kf2, kf3); \
            mma16816(sc[par_][0], qa[s2], kf0, kf1);                             \
            mma16816(sc[par_][1], qa[s2], kf2, kf3);                             \
        }                                                                        \
    } while (0)

__global__ __launch_bounds__(128, 4) void k_attn(float* __restrict__ Out) {
    __shared__ __align__(16) char smem[SMEM_SZ];   // 18432
    const uint32_t sb = smem_u32(smem);

    const int tid  = threadIdx.x;
    const int w    = tid >> 5;
    const int lane = tid & 31;
    const int head = blockIdx.y;
    const int q0   = blockIdx.x * QTILE;
    const int hb   = head * DH;

    const int lm = lane >> 3, lr = lane & 7;
    const int sKey = ((lm >> 1) << 3) + lr;
    const int sD   = (lm & 1) << 3;
    const int vKey = ((lm & 1) << 3) + lr;
    const int vD   = (lm >> 1) << 3;
    const int qRow = ((lm & 1) << 3) + lr;
    const int qCol = (lm >> 1) << 3;

    // ---- stage Q (64 rows) into stage-0 area, read fragments to registers ----
    {
        const int r = tid >> 1, cb = (tid & 1) * 4;
        const uint32_t d0 = sb + r * PITCH + cb * 16;
        const __half* qh = &g_qh[(size_t)(q0 + r) * F_OUT + hb];
        #pragma unroll
        for (int c = 0; c < 4; c++) cpa16(d0 + c * 16, qh + (cb + c) * 8);
    }
    CP_COMMIT();
    CP_WAIT0();
    __syncthreads();

    uint32_t qa[4][4];
    {
        const uint32_t qb = sb + (w * 16 + qRow) * PITCH + qCol * 2;
        #pragma unroll
        for (int s = 0; s < 4; s++)
            ldsm4(qb + s * 32, qa[s][0], qa[s][1], qa[s][2], qa[s][3]);
    }
    __syncthreads();   // Q staging area now free for K tiles

    // ---- prologue: K tile 0 into stage 0 ----
    {
        const int r = tid >> 1, cb = (tid & 1) * 4;
        const uint32_t d0 = sb + r * PITCH + cb * 16;
        const __half* kh = &g_hh[(size_t)r * F_OUT + hb];
        #pragma unroll
        for (int c = 0; c < 4; c++) cpa16(d0 + c * 16, kh + (cb + c) * 8);
    }
    CP_COMMIT();

    float oc[8][4];
    #pragma unroll
    for (int j = 0; j < 8; j++)
        #pragma unroll
        for (int k = 0; k < 4; k++) oc[j][k] = 0.f;
    float lsum[2] = {};

    for (int t = 0; t < NT; t++) {
        CP_WAIT0();
        __syncthreads();
        const uint32_t stg = sb + (t & 1) * STG;

        if (t + 1 < NT) {
            const int r = tid >> 1, cb = (tid & 1) * 4;
            const uint32_t d0 = sb + ((t + 1) & 1) * STG + r * PITCH + cb * 16;
            const __half* kh = &g_hh[(size_t)((t + 1) * KTILE + r) * F_OUT + hb];
            #pragma unroll
            for (int c = 0; c < 4; c++) cpa16(d0 + c * 16, kh + (cb + c) * 8);
        }
        CP_COMMIT();

        const uint32_t sAddr = stg + sKey * PITCH + sD * 2;
        const uint32_t vAddr = stg + vKey * PITCH + vD * 2;

        float sc[2][2][4];   // [parity][nhalf][4]
        S_BLOCK(0);

        #pragma unroll
        for (int u = 0; u < 4; u++) {
            const int cur = u & 1;
            if (u < 3) S_BLOCK(u + 1);   // keep tensor pipe busy during softmax(u)

            uint32_t pa[4];
            pa[0] = softmax_pair(sc[cur][0][0], sc[cur][0][1], lsum[0]);
            pa[1] = softmax_pair(sc[cur][0][2], sc[cur][0][3], lsum[1]);
            pa[2] = softmax_pair(sc[cur][1][0], sc[cur][1][1], lsum[0]);
            pa[3] = softmax_pair(sc[cur][1][2], sc[cur][1][3], lsum[1]);

            #pragma unroll
            for (int d = 0; d < 4; d++) {
                const uint32_t a = vAddr + (16 * u) * PITCH + (16 * d) * 2;
                uint32_t h0, h1, h2, h3;
                ldsm4t(a, h0, h1, h2, h3);
                mma16816(oc[2 * d],     pa, h0, h1);
                mma16816(oc[2 * d + 1], pa, h2, h3);
            }
        }
    }

    // ---- reduce lsum across quad, normalize, write O ----
    const int g  = lane >> 2, tg = lane & 3;
    float lA = lsum[0], lB = lsum[1];
    lA += __shfl_xor_sync(0xffffffffu, lA, 1);
    lA += __shfl_xor_sync(0xffffffffu, lA, 2);
    lB += __shfl_xor_sync(0xffffffffu, lB, 1);
    lB += __shfl_xor_sync(0xffffffffu, lB, 2);
    const float invA = 1.0f / lA, invB = 1.0f / lB;

    const int rowA = q0 + w * 16 + g;
    float* outA = &Out[(size_t)rowA * F_OUT + hb + 2 * tg];
    float* outB = outA + 8 * F_OUT;
    #pragma unroll
    for (int j = 0; j < 8; j++) {
        *(float2*)(outA + 8 * j) = make_float2(oc[j][0] * invA, oc[j][1] * invA);
        *(float2*)(outB + 8 * j) = make_float2(oc[j][2] * invB, oc[j][3] * invB);
    }
}

// ---------------------------------------------------------------------------
extern "C" void kernel_launch(void* const* d_in, const int* in_sizes, int n_in,
                              void* d_out, int out_size) {
    const float* x = (const float*)d_in[0];
    // d_in[1] = adj (unused by the reference forward)
    const float* W = (const float*)d_in[2];
    const float* A = (const float*)d_in[3];
    float* out = (float*)d_out;

    k_cvt<<<(N_X + N_W + N_A) / 512, 256>>>(x, W, A);
    k_mm1<<<dim3(N_NODES / 128, F_OUT / 64), 128>>>();
    k_mm2<<<dim3(N_NODES / 128, HEADS), 128>>>();
    k_attn<<<dim3(N_NODES / QTILE, HEADS), 128>>>(out);
}

// round 16
// speedup vs baseline: 1.0405x; 1.0405x over previous
#include <cuda_runtime.h>
#include <cuda_fp16.h>
#include <math.h>
#include <stdint.h>

#define N_NODES 4096
#define F_IN    256
#define F_OUT   512
#define HEADS   8
#define DH      64
#define LOG2E   1.4426950408889634f
#define MAGICF  12582912.0f          // 1.5 * 2^23

#define KTILE   64
#define NT      (N_NODES / KTILE)   // 64 key tiles
#define QTILE   128                 // q rows per block (32 per warp)
#define PITCH   144                 // bytes per 64-fp16 row (conflict-free)
#define STG     (KTILE * PITCH)     // 9216 bytes per K stage
#define QSM     (QTILE * PITCH)     // 18432 bytes Q region
#define ASMEM   (QSM + 2 * STG)     // 36864

#define N_X (N_NODES * F_IN)
#define N_W (F_OUT * F_IN)
#define N_A (HEADS * DH * DH)

typedef unsigned long long u64;

// ---------------- device scratch (no allocs allowed) ----------------
__device__ __align__(256) __half g_xh[N_X], g_xl[N_X];
__device__ __align__(256) __half g_wh[N_W], g_wl[N_W];
__device__ __align__(256) __half g_ah[N_A], g_al[N_A];
__device__ __align__(256) __half g_hh[N_NODES * F_OUT];   // fp16(h)  (K == V)
__device__ __align__(256) __half g_hl[N_NODES * F_OUT];   // fp16 residual of h
__device__ __align__(256) __half g_qh[N_NODES * F_OUT];   // fp16(q * log2e)

// ---------------- helpers ----------------
__device__ __forceinline__ uint32_t smem_u32(const void* p) {
    uint32_t a;
    asm("{ .reg .u64 t; cvta.to.shared.u64 t, %1; cvt.u32.u64 %0, t; }" : "=r"(a) : "l"(p));
    return a;
}
__device__ __forceinline__ uint32_t hfpk(float a, float b) {
    uint32_t r; asm("cvt.rn.f16x2.f32 %0, %1, %2;" : "=r"(r) : "f"(b), "f"(a)); return r;
}
__device__ __forceinline__ u64 pk2(float lo, float hi) {
    u64 r; asm("mov.b64 %0, {%1, %2};" : "=l"(r) : "f"(lo), "f"(hi)); return r;
}
__device__ __forceinline__ u64 dup2(float v) {
    u64 r; asm("mov.b64 %0, {%1, %1};" : "=l"(r) : "f"(v)); return r;
}
__device__ __forceinline__ void unp2(u64 v, float& lo, float& hi) {
    asm("mov.b64 {%0, %1}, %2;" : "=f"(lo), "=f"(hi) : "l"(v));
}
__device__ __forceinline__ u64 add2(u64 a, u64 b) {
    u64 r; asm("add.rn.f32x2 %0, %1, %2;" : "=l"(r) : "l"(a), "l"(b)); return r;
}
__device__ __forceinline__ u64 fma2_(u64 a, u64 b, u64 c) {
    u64 r; asm("fma.rn.f32x2 %0, %1, %2, %3;" : "=l"(r) : "l"(a), "l"(b), "l"(c)); return r;
}

// packed softmax: p = 2^(leaky(v) - 6) for a pair; accumulates lsum; returns fp16x2
__device__ __forceinline__ uint32_t softmax_pair(float c0, float c1, float& lacc) {
    u64 v2 = pk2(c0, c1);
    u64 y2 = fma2_(v2, dup2(0.6f), dup2(-6.0f));        // 0.6v - 6
    u64 a2 = v2 & 0x7FFFFFFF7FFFFFFFull;                // |v|
    y2 = fma2_(a2, dup2(0.4f), y2);                     // leaky - 6
    u64 fn2 = add2(y2, dup2(MAGICF));
    u64 t2  = fma2_(fn2, dup2(1.0f), dup2(-MAGICF));    // round(y)
    u64 f2  = fma2_(t2, dup2(-1.0f), y2);               // frac in [-0.5, 0.5]
    u64 p2  = fma2_(f2, dup2(0.00961813f), dup2(0.05550411f));
    p2 = fma2_(p2, f2, dup2(0.24022651f));
    p2 = fma2_(p2, f2, dup2(0.69314718f));
    p2 = fma2_(p2, f2, dup2(1.0f));
    float pf0, pf1, ff0, ff1;
    unp2(p2, pf0, pf1);
    unp2(fn2, ff0, ff1);
    float e0 = __int_as_float(__float_as_int(pf0) + (__float_as_int(ff0) << 23));
    float e1 = __int_as_float(__float_as_int(pf1) + (__float_as_int(ff1) << 23));
    lacc += e0 + e1;
    return hfpk(e0, e1);
}

__device__ __forceinline__ void cpa16(uint32_t dst, const void* src) {
    asm volatile("cp.async.cg.shared.global [%0], [%1], 16;" :: "r"(dst), "l"(src) : "memory");
}
#define CP_COMMIT() asm volatile("cp.async.commit_group;" ::: "memory")
#define CP_WAIT0()  asm volatile("cp.async.wait_group 0;" ::: "memory")
#define CP_WAIT1()  asm volatile("cp.async.wait_group 1;" ::: "memory")

__device__ __forceinline__ void ldsm4(uint32_t a, uint32_t& r0, uint32_t& r1,
                                      uint32_t& r2, uint32_t& r3) {
    asm volatile("ldmatrix.sync.aligned.m8n8.x4.shared.b16 {%0,%1,%2,%3}, [%4];"
                 : "=r"(r0), "=r"(r1), "=r"(r2), "=r"(r3) : "r"(a));
}
__device__ __forceinline__ void ldsm4t(uint32_t a, uint32_t& r0, uint32_t& r1,
                                       uint32_t& r2, uint32_t& r3) {
    asm volatile("ldmatrix.sync.aligned.m8n8.x4.trans.shared.b16 {%0,%1,%2,%3}, [%4];"
                 : "=r"(r0), "=r"(r1), "=r"(r2), "=r"(r3) : "r"(a));
}
__device__ __forceinline__ void mma16816(float* c, const uint32_t* a, uint32_t b0, uint32_t b1) {
    asm volatile(
        "mma.sync.aligned.m16n8k16.row.col.f32.f16.f16.f32 "
        "{%0,%1,%2,%3}, {%4,%5,%6,%7}, {%8,%9}, {%0,%1,%2,%3};"
        : "+f"(c[0]), "+f"(c[1]), "+f"(c[2]), "+f"(c[3])
        : "r"(a[0]), "r"(a[1]), "r"(a[2]), "r"(a[3]), "r"(b0), "r"(b1));
}

// ---------------------------------------------------------------------------
// Kernel 0: convert x, W, A to fp16 hi/lo pairs.
// ---------------------------------------------------------------------------
__global__ __launch_bounds__(256) void k_cvt(const float* __restrict__ X,
                                             const float* __restrict__ W,
                                             const float* __restrict__ A) {
    const int i = (blockIdx.x * 256 + threadIdx.x) * 2;
    const float* src; __half *dh, *dl; int off;
    if (i < N_X)            { src = X; dh = g_xh; dl = g_xl; off = i; }
    else if (i < N_X + N_W) { src = W; dh = g_wh; dl = g_wl; off = i - N_X; }
    else                    { src = A; dh = g_ah; dl = g_al; off = i - N_X - N_W; }
    float2 v = *(const float2*)&src[off];
    uint32_t hp = hfpk(v.x, v.y);
    __half2 h2 = *(__half2*)&hp;
    uint32_t lp = hfpk(v.x - __low2float(h2), v.y - __high2float(h2));
    *(uint32_t*)&dh[off] = hp;
    *(uint32_t*)&dl[off] = lp;
}

// ---------------------------------------------------------------------------
// Kernel 1: h = x @ W^T via 3-term compensated fp16 mma.
// NOW double-buffered across the 8 k-chunks (dynamic smem, 2 stages).
// ---------------------------------------------------------------------------
#define P80      80
#define MM1_XH   0
#define MM1_XL   10240
#define MM1_WH   20480
#define MM1_WL   25600
#define MM1_STG  30720
#define MM1_SMEM (2 * MM1_STG)   // 61440

__global__ __launch_bounds__(128) void k_mm1() {
    extern __shared__ __align__(16) char mm1smem[];
    const uint32_t sb = smem_u32(mm1smem);
    const int tid = threadIdx.x, w = tid >> 5, lane = tid & 31;
    const int m0 = blockIdx.x * 128, o0 = blockIdx.y * 64;
    const int lm = lane >> 3, lr = lane & 7;
    const int sKey = ((lm >> 1) << 3) + lr;
    const int sD   = (lm & 1) << 3;
    const int qRow = ((lm & 1) << 3) + lr;
    const int qCol = (lm >> 1) << 3;

    const int wr = tid & 63;   // W row handled by this thread (hi if tid<64 else lo)

    // prologue: load chunk 0 into stage 0
    {
        const __half* xh = &g_xh[(size_t)(m0 + tid) * F_IN];
        const __half* xl = &g_xl[(size_t)(m0 + tid) * F_IN];
        #pragma unroll
        for (int c = 0; c < 4; c++) {
            cpa16(sb + MM1_XH + tid * P80 + c * 16, xh + c * 8);
            cpa16(sb + MM1_XL + tid * P80 + c * 16, xl + c * 8);
        }
        const __half* ws = (tid < 64) ? &g_wh[(size_t)(o0 + wr) * F_IN]
                                      : &g_wl[(size_t)(o0 + wr) * F_IN];
        const uint32_t dw = sb + ((tid < 64) ? MM1_WH : MM1_WL) + wr * P80;
        #pragma unroll
        for (int c = 0; c < 4; c++) cpa16(dw + c * 16, ws + c * 8);
    }
    CP_COMMIT();

    float oc[2][8][4] = {};

    for (int kc = 0; kc < F_IN / 32; kc++) {
        // prefetch chunk kc+1 into other stage (its stage was freed by the
        // __syncthreads at the end of iteration kc-1)
        if (kc + 1 < F_IN / 32) {
            const int k1 = (kc + 1) * 32;
            const uint32_t st = sb + ((kc + 1) & 1) * MM1_STG;
            const __half* xh = &g_xh[(size_t)(m0 + tid) * F_IN + k1];
            const __half* xl = &g_xl[(size_t)(m0 + tid) * F_IN + k1];
            #pragma unroll
            for (int c = 0; c < 4; c++) {
                cpa16(st + MM1_XH + tid * P80 + c * 16, xh + c * 8);
                cpa16(st + MM1_XL + tid * P80 + c * 16, xl + c * 8);
            }
            const __half* ws = (tid < 64) ? &g_wh[(size_t)(o0 + wr) * F_IN + k1]
                                          : &g_wl[(size_t)(o0 + wr) * F_IN + k1];
            const uint32_t dw = st + ((tid < 64) ? MM1_WH : MM1_WL) + wr * P80;
            #pragma unroll
            for (int c = 0; c < 4; c++) cpa16(dw + c * 16, ws + c * 8);
            CP_COMMIT();
            CP_WAIT1();            // chunk kc complete; kc+1 may stream
        } else {
            CP_WAIT0();
        }
        __syncthreads();

        const uint32_t st = sb + (kc & 1) * MM1_STG;

        uint32_t ah[4][4], al[4][4];
        #pragma unroll
        for (int m = 0; m < 2; m++) {
            const uint32_t bh = st + MM1_XH + (w * 32 + m * 16 + qRow) * P80 + qCol * 2;
            const uint32_t bl = st + MM1_XL + (w * 32 + m * 16 + qRow) * P80 + qCol * 2;
            #pragma unroll
            for (int s = 0; s < 2; s++) {
                ldsm4(bh + s * 32, ah[s * 2 + m][0], ah[s * 2 + m][1],
                                   ah[s * 2 + m][2], ah[s * 2 + m][3]);
                ldsm4(bl + s * 32, al[s * 2 + m][0], al[s * 2 + m][1],
                                   al[s * 2 + m][2], al[s * 2 + m][3]);
            }
        }
        #pragma unroll
        for (int s = 0; s < 2; s++) {
            #pragma unroll
            for (int u = 0; u < 4; u++) {
                uint32_t bh0, bh1, bh2, bh3, bl0, bl1, bl2, bl3;
                ldsm4(st + MM1_WH + (u * 16 + sKey) * P80 + s * 32 + sD * 2, bh0, bh1, bh2, bh3);
                ldsm4(st + MM1_WL + (u * 16 + sKey) * P80 + s * 32 + sD * 2, bl0, bl1, bl2, bl3);
                #pragma unroll
                for (int m = 0; m < 2; m++) {
                    mma16816(oc[m][2 * u],     ah[s * 2 + m], bh0, bh1);
                    mma16816(oc[m][2 * u],     al[s * 2 + m], bh0, bh1);
                    mma16816(oc[m][2 * u],     ah[s * 2 + m], bl0, bl1);
                    mma16816(oc[m][2 * u + 1], ah[s * 2 + m], bh2, bh3);
                    mma16816(oc[m][2 * u + 1], al[s * 2 + m], bh2, bh3);
                    mma16816(oc[m][2 * u + 1], ah[s * 2 + m], bl2, bl3);
                }
            }
        }
        __syncthreads();   // stage (kc&1) free for chunk kc+2's prefetch
    }

    const int g = lane >> 2, tg = lane & 3;
    #pragma unroll
    for (int m = 0; m < 2; m++) {
        const int rowA = m0 + w * 32 + m * 16 + g;
        #pragma unroll
        for (int j = 0; j < 8; j++) {
            const int col = o0 + j * 8 + 2 * tg;
            float a0 = oc[m][j][0], a1 = oc[m][j][1];
            uint32_t hp = hfpk(a0, a1);
            __half2 h2 = *(__half2*)&hp;
            *(uint32_t*)&g_hh[(size_t)rowA * F_OUT + col] = hp;
            *(uint32_t*)&g_hl[(size_t)rowA * F_OUT + col] =
                hfpk(a0 - __low2float(h2), a1 - __high2float(h2));
            float b0 = oc[m][j][2], b1 = oc[m][j][3];
            uint32_t hp2 = hfpk(b0, b1);
            __half2 h22 = *(__half2*)&hp2;
            *(uint32_t*)&g_hh[(size_t)(rowA + 8) * F_OUT + col] = hp2;
            *(uint32_t*)&g_hl[(size_t)(rowA + 8) * F_OUT + col] =
                hfpk(b0 - __low2float(h22), b1 - __high2float(h22));
        }
    }
}

// ---------------------------------------------------------------------------
// Kernel 2: q = (h @ A) * log2e via 3-term compensated fp16 mma.
// NOW single-shot: h-tile (full 64 head-cols) + A hi/lo in ONE cp.async group.
// ---------------------------------------------------------------------------
#define MM2_MH   0
#define MM2_ML   18432
#define MM2_AH   36864
#define MM2_AL   46080
#define MM2_SMEM 55296

__global__ __launch_bounds__(128) void k_mm2() {
    extern __shared__ __align__(16) char mm2smem[];
    const uint32_t sb = smem_u32(mm2smem);
    const int tid = threadIdx.x, w = tid >> 5, lane = tid & 31;
    const int m0 = blockIdx.x * 128, head = blockIdx.y, hb = head * DH;
    const int lm = lane >> 3, lr = lane & 7;
    const int vKey = ((lm & 1) << 3) + lr;
    const int vD   = (lm >> 1) << 3;
    const int qRow = ((lm & 1) << 3) + lr;
    const int qCol = (lm >> 1) << 3;

    // single cp.async group: h rows (hi+lo) + A[head] (hi+lo)
    {
        const __half* hh = &g_hh[(size_t)(m0 + tid) * F_OUT + hb];
        const __half* hl = &g_hl[(size_t)(m0 + tid) * F_OUT + hb];
        const uint32_t dmh = sb + MM2_MH + tid * PITCH;
        const uint32_t dml = sb + MM2_ML + tid * PITCH;
        #pragma unroll
        for (int c = 0; c < 8; c++) {
            cpa16(dmh + c * 16, hh + c * 8);
            cpa16(dml + c * 16, hl + c * 8);
        }
        const int r = tid & 63;
        const __half* as = (tid < 64) ? &g_ah[(size_t)head * DH * DH + r * DH]
                                      : &g_al[(size_t)head * DH * DH + r * DH];
        const uint32_t da = sb + ((tid < 64) ? MM2_AH : MM2_AL) + r * PITCH;
        #pragma unroll
        for (int c = 0; c < 8; c++) cpa16(da + c * 16, as + c * 8);
    }
    CP_COMMIT();
    CP_WAIT0();
    __syncthreads();

    uint32_t ah[8][4], al[8][4];   // [s*2+m], s=0..3
    #pragma unroll
    for (int m = 0; m < 2; m++) {
        const uint32_t bh = sb + MM2_MH + (w * 32 + m * 16 + qRow) * PITCH + qCol * 2;
        const uint32_t bl = sb + MM2_ML + (w * 32 + m * 16 + qRow) * PITCH + qCol * 2;
        #pragma unroll
        for (int s = 0; s < 4; s++) {
            ldsm4(bh + s * 32, ah[s * 2 + m][0], ah[s * 2 + m][1],
                               ah[s * 2 + m][2], ah[s * 2 + m][3]);
            ldsm4(bl + s * 32, al[s * 2 + m][0], al[s * 2 + m][1],
                               al[s * 2 + m][2], al[s * 2 + m][3]);
        }
    }

    float oc[2][8][4] = {};
    #pragma unroll
    for (int s = 0; s < 4; s++) {
        #pragma unroll
        for (int u = 0; u < 4; u++) {
            uint32_t bh0, bh1, bh2, bh3, bl0, bl1, bl2, bl3;
            ldsm4t(sb + MM2_AH + (s * 16 + vKey) * PITCH + (u * 16 + vD) * 2, bh0, bh1, bh2, bh3);
            ldsm4t(sb + MM2_AL + (s * 16 + vKey) * PITCH + (u * 16 + vD) * 2, bl0, bl1, bl2, bl3);
            #pragma unroll
            for (int m = 0; m < 2; m++) {
                mma16816(oc[m][2 * u],     ah[s * 2 + m], bh0, bh1);
                mma16816(oc[m][2 * u],     al[s * 2 + m], bh0, bh1);
                mma16816(oc[m][2 * u],     ah[s * 2 + m], bl0, bl1);
                mma16816(oc[m][2 * u + 1], ah[s * 2 + m], bh2, bh3);
                mma16816(oc[m][2 * u + 1], al[s * 2 + m], bh2, bh3);
                mma16816(oc[m][2 * u + 1], ah[s * 2 + m], bl2, bl3);
            }
        }
    }

    const int g = lane >> 2, tg = lane & 3;
    #pragma unroll
    for (int m = 0; m < 2; m++) {
        const int rowA = m0 + w * 32 + m * 16 + g;
        #pragma unroll
        for (int j = 0; j < 8; j++) {
            const int col = hb + j * 8 + 2 * tg;
            *(uint32_t*)&g_qh[(size_t)rowA * F_OUT + col] =
                hfpk(oc[m][j][0] * LOG2E, oc[m][j][1] * LOG2E);
            *(uint32_t*)&g_qh[(size_t)(rowA + 8) * F_OUT + col] =
                hfpk(oc[m][j][2] * LOG2E, oc[m][j][3] * LOG2E);
        }
    }
}

// ---------------------------------------------------------------------------
// Kernel 3: fp16 flash attention (exact R13 version — best measured config):
// QTILE 128, 2 blocks/SM, packed-f32x2 softmax, S(u+1) pipelined ahead,
// Q fragments reloaded from dedicated smem region.
// ---------------------------------------------------------------------------
#define S_BLOCK(uu)                                                              \
    do {                                                                         \
        const int par_ = (uu) & 1;                                               \
        _Pragma("unroll")                                                        \
        for (int m2 = 0; m2 < 2; m2++)                                           \
            _Pragma("unroll")                                                    \
            for (int k2 = 0; k2 < 4; k2++) {                                     \
                sc[par_][m2][0][k2] = 0.f; sc[par_][m2][1][k2] = 0.f;            \
            }                                                                    \
        _Pragma("unroll")                                                        \
        for (int s2 = 0; s2 < 4; s2++) {                                         \
            uint32_t kf0, kf1, kf2, kf3;                                         \
            ldsm4(sAddr + (16 * (uu)) * PITCH + (16 * s2) * 2,                   \
                  kf0, kf1, kf2, kf3);                                           \
            _Pragma("unroll")                                                    \
            for (int m2 = 0; m2 < 2; m2++) {                                     \
                uint32_t qv[4];                                                  \
                ldsm4(qBase + (m2 * 16) * PITCH + s2 * 32,                       \
                      qv[0], qv[1], qv[2], qv[3]);                               \
                mma16816(sc[par_][m2][0], qv, kf0, kf1);                         \
                mma16816(sc[par_][m2][1], qv, kf2, kf3);                         \
            }                                                                    \
        }                                                                        \
    } while (0)

__global__ __launch_bounds__(128, 2) void k_attn(float* __restrict__ Out) {
    __shared__ __align__(16) char smem[ASMEM];   // Q 18432 + 2 K stages 18432
    const uint32_t sb  = smem_u32(smem);
    const uint32_t sbK = sb + QSM;

    const int tid  = threadIdx.x;
    const int w    = tid >> 5;
    const int lane = tid & 31;
    const int head = blockIdx.y;
    const int q0   = blockIdx.x * QTILE;
    const int hb   = head * DH;

    const int lm = lane >> 3, lr = lane & 7;
    const int sKey = ((lm >> 1) << 3) + lr;
    const int sD   = (lm & 1) << 3;
    const int vKey = ((lm & 1) << 3) + lr;
    const int vD   = (lm >> 1) << 3;
    const int qRow = ((lm & 1) << 3) + lr;
    const int qCol = (lm >> 1) << 3;

    // ---- prologue: Q tile + K tile 0 in one cp.async group ----
    {
        const int r = tid;
        const __half* qh = &g_qh[(size_t)(q0 + r) * F_OUT + hb];
        const uint32_t d0 = sb + r * PITCH;
        #pragma unroll
        for (int c = 0; c < 8; c++) cpa16(d0 + c * 16, qh + c * 8);
        const int r2 = tid >> 1, cb = (tid & 1) * 4;
        const uint32_t dk = sbK + r2 * PITCH + cb * 16;
        const __half* kh = &g_hh[(size_t)r2 * F_OUT + hb];
        #pragma unroll
        for (int c = 0; c < 4; c++) cpa16(dk + c * 16, kh + (cb + c) * 8);
    }
    CP_COMMIT();

    const uint32_t qBase = sb + (w * 32 + qRow) * PITCH + qCol * 2;

    float oc[2][8][4];
    #pragma unroll
    for (int m = 0; m < 2; m++)
        #pragma unroll
        for (int j = 0; j < 8; j++)
            #pragma unroll
            for (int k = 0; k < 4; k++) oc[m][j][k] = 0.f;
    float lsum[2][2] = {};

    for (int t = 0; t < NT; t++) {
        CP_WAIT0();
        __syncthreads();
        const uint32_t stg = sbK + (t & 1) * STG;

        if (t + 1 < NT) {
            const int r = tid >> 1, cb = (tid & 1) * 4;
            const uint32_t d0 = sbK + ((t + 1) & 1) * STG + r * PITCH + cb * 16;
            const __half* kh = &g_hh[(size_t)((t + 1) * KTILE + r) * F_OUT + hb];
            #pragma unroll
            for (int c = 0; c < 4; c++) cpa16(d0 + c * 16, kh + (cb + c) * 8);
        }
        CP_COMMIT();

        const uint32_t sAddr = stg + sKey * PITCH + sD * 2;
        const uint32_t vAddr = stg + vKey * PITCH + vD * 2;

        float sc[2][2][2][4];   // [parity][m][nhalf][4]
        S_BLOCK(0);

        #pragma unroll
        for (int u = 0; u < 4; u++) {
            const int cur = u & 1;
            if (u < 3) S_BLOCK(u + 1);   // fill tensor pipe during softmax(u)

            uint32_t pa[2][4];
            #pragma unroll
            for (int m = 0; m < 2; m++) {
                pa[m][0] = softmax_pair(sc[cur][m][0][0], sc[cur][m][0][1], lsum[m][0]);
                pa[m][1] = softmax_pair(sc[cur][m][0][2], sc[cur][m][0][3], lsum[m][1]);
                pa[m][2] = softmax_pair(sc[cur][m][1][0], sc[cur][m][1][1], lsum[m][0]);
                pa[m][3] = softmax_pair(sc[cur][m][1][2], sc[cur][m][1][3], lsum[m][1]);
            }

            #pragma unroll
            for (int d = 0; d < 4; d++) {
                const uint32_t a = vAddr + (16 * u) * PITCH + (16 * d) * 2;
                uint32_t h0, h1, h2, h3;
                ldsm4t(a, h0, h1, h2, h3);
                #pragma unroll
                for (int m = 0; m < 2; m++) {
                    mma16816(oc[m][2 * d],     pa[m], h0, h1);
                    mma16816(oc[m][2 * d + 1], pa[m], h2, h3);
                }
            }
        }
    }

    // ---- reduce lsum across quad, normalize, write O ----
    const int g  = lane >> 2, tg = lane & 3;
    #pragma unroll
    for (int m = 0; m < 2; m++) {
        float lA = lsum[m][0], lB = lsum[m][1];
        lA += __shfl_xor_sync(0xffffffffu, lA, 1);
        lA += __shfl_xor_sync(0xffffffffu, lA, 2);
        lB += __shfl_xor_sync(0xffffffffu, lB, 1);
        lB += __shfl_xor_sync(0xffffffffu, lB, 2);
        const float invA = 1.0f / lA, invB = 1.0f / lB;

        const int rowA = q0 + w * 32 + m * 16 + g;
        float* outA = &Out[(size_t)rowA * F_OUT + hb + 2 * tg];
        float* outB = outA + 8 * F_OUT;
        #pragma unroll
        for (int j = 0; j < 8; j++) {
            *(float2*)(outA + 8 * j) = make_float2(oc[m][j][0] * invA, oc[m][j][1] * invA);
            *(float2*)(outB + 8 * j) = make_float2(oc[m][j][2] * invB, oc[m][j][3] * invB);
        }
    }
}

// ---------------------------------------------------------------------------
extern "C" void kernel_launch(void* const* d_in, const int* in_sizes, int n_in,
                              void* d_out, int out_size) {
    const float* x = (const float*)d_in[0];
    // d_in[1] = adj (unused by the reference forward)
    const float* W = (const float*)d_in[2];
    const float* A = (const float*)d_in[3];
    float* out = (float*)d_out;

    static bool attr_done = false;
    if (!attr_done) {
        cudaFuncSetAttribute(k_mm1, cudaFuncAttributeMaxDynamicSharedMemorySize, MM1_SMEM);
        cudaFuncSetAttribute(k_mm2, cudaFuncAttributeMaxDynamicSharedMemorySize, MM2_SMEM);
        attr_done = true;
    }

    k_cvt<<<(N_X + N_W + N_A) / 512, 256>>>(x, W, A);
    k_mm1<<<dim3(N_NODES / 128, F_OUT / 64), 128, MM1_SMEM>>>();
    k_mm2<<<dim3(N_NODES / 128, HEADS), 128, MM2_SMEM>>>();
    k_attn<<<dim3(N_NODES / QTILE, HEADS), 128>>>(out);
}